// round 2
// baseline (speedup 1.0000x reference)
#include <cuda_runtime.h>
#include <cstdint>
#include <cstddef>

#define N_NODES 20000
#define N_EDGES 320000

// constants
#define LOG2_C       0.6931471805599453f
#define INV_SQRT3_C  0.5773502691896258f
#define INV_SQRT8_C  0.35355339059327373f   // 1/sqrt(NBASIS)
#define W_SCALE      0.125f                 // 1/sqrt(NHID=64)
#define INV_MUL_C    0.125f                 // 1/sqrt(MUL=64)
#define SC_A_C       0.02209708691207961f   // 1/sqrt(2*MUL) * 1/sqrt(16)
#define SC_B_C       0.04419417382415922f   // 1/sqrt(MUL*NATTR)

// scratch (device globals: allocation-free rule)
__device__ __align__(1024) float d_sv[(size_t)N_NODES * 256];   // [s(64) | v(u*3+c) 192] per node
__device__ __align__(1024) float d_agg[(size_t)N_NODES * 512];  // [agg_s(128) | agg_v(m*3+c) 384]

__device__ __forceinline__ unsigned smem_u32(const void* p) {
    return (unsigned)__cvta_generic_to_shared(p);
}

// ---------------------------------------------------------------------------
// zero the aggregation buffer
// ---------------------------------------------------------------------------
__global__ void zero_agg_kernel() {
    size_t i = (size_t)blockIdx.x * blockDim.x + threadIdx.x;
    float4* p = reinterpret_cast<float4*>(d_agg);
    if (i < (size_t)N_NODES * 128) p[i] = make_float4(0.f, 0.f, 0.f, 0.f);
}

// ---------------------------------------------------------------------------
// node prep: s = s0 @ W1s * inv_mul ; v[:,:,c] = v0[:,:,c] @ W1v * inv_mul
// layout into d_sv: [s(64) | v(w*3+c)]
// ---------------------------------------------------------------------------
__global__ void __launch_bounds__(256)
nodeprep_kernel(const float* __restrict__ node_feat,
                const float* __restrict__ W1s,
                const float* __restrict__ W1v)
{
    __shared__ float sW1s[4096];
    __shared__ float sW1v[4096];
    __shared__ float sNF[4][256];

    const int tid = threadIdx.x;
    for (int i = tid; i < 4096; i += 256) { sW1s[i] = W1s[i]; sW1v[i] = W1v[i]; }
    __syncthreads();

    const int ngroups = (N_NODES + 3) / 4;
    for (int g = blockIdx.x; g < ngroups; g += gridDim.x) {
        const int n0 = g * 4;
        __syncthreads();
        for (int i = tid; i < 1024; i += 256) {
            const int nl = i >> 8, j = i & 255;
            const int n = n0 + nl;
            sNF[nl][j] = (n < N_NODES) ? node_feat[(size_t)n * 256 + j] : 0.f;
        }
        __syncthreads();
        const int nl = tid >> 6, w = tid & 63;
        const int n = n0 + nl;
        if (n < N_NODES) {
            float sacc = 0.f, v0a = 0.f, v1a = 0.f, v2a = 0.f;
#pragma unroll
            for (int u = 0; u < 64; ++u) {
                const float ws = sW1s[u * 64 + w];
                const float wv = sW1v[u * 64 + w];
                sacc = fmaf(sNF[nl][u], ws, sacc);
                v0a  = fmaf(sNF[nl][64 + 3 * u + 0], wv, v0a);
                v1a  = fmaf(sNF[nl][64 + 3 * u + 1], wv, v1a);
                v2a  = fmaf(sNF[nl][64 + 3 * u + 2], wv, v2a);
            }
            float* o = d_sv + (size_t)n * 256;
            o[w] = sacc * INV_MUL_C;
            o[64 + 3 * w + 0] = v0a * INV_MUL_C;
            o[64 + 3 * w + 1] = v1a * INV_MUL_C;
            o[64 + 3 * w + 2] = v2a * INV_MUL_C;
        }
    }
}

// ---------------------------------------------------------------------------
// edge kernel: fused FC1 -> softplus -> FC2 -> gather -> tensor product ->
// bulk-reduce scatter into d_agg. 4 edges per block iteration.
// thread tid owns Wfc2 column tid (64 floats in registers).
// ---------------------------------------------------------------------------
__global__ void __launch_bounds__(256, 2)
edge_kernel(const float* __restrict__ edge_sh,
            const float* __restrict__ edge_basis,
            const float* __restrict__ Wfc1,
            const float* __restrict__ Wfc2,
            const int*   __restrict__ edge_idx)
{
    __shared__ float sWfc1[512];
    __shared__ __align__(16) float sH[4][64];
    __shared__ __align__(16) float sOut[2][4][512];
    __shared__ int    sSrc[4];
    __shared__ int    sDst[4];
    __shared__ float4 sSh[4];

    const int tid = threadIdx.x;

    float wcol[64];
#pragma unroll
    for (int k = 0; k < 64; ++k) wcol[k] = Wfc2[k * 256 + tid];
    for (int i = tid; i < 512; i += 256) sWfc1[i] = Wfc1[i];
    __syncthreads();

    const int niter = N_EDGES / 4;   // E divisible by 4
    int li = 0;
    for (int it = blockIdx.x; it < niter; it += gridDim.x, ++li) {
        const int e0 = it * 4;
        const int r = li & 1;

        // slot r was consumed by the bulk-reduce issued 2 iterations ago
        if (tid < 4) asm volatile("cp.async.bulk.wait_group 1;" ::: "memory");

        // phase A: h for 4 edges (64 threads each)
        {
            const int el = tid >> 6, k = tid & 63;
            const int e = e0 + el;
            const float* bb = edge_basis + (size_t)e * 8;
            float acc = 0.f;
#pragma unroll
            for (int b = 0; b < 8; ++b) acc = fmaf(__ldg(bb + b), sWfc1[b * 64 + k], acc);
            acc *= INV_SQRT8_C;
            const float sp = fmaxf(acc, 0.f) + log1pf(expf(-fabsf(acc)));
            sH[el][k] = sp - LOG2_C;
        }
        if (tid < 4) {
            const int e = e0 + tid;
            sSh[tid] = *reinterpret_cast<const float4*>(edge_sh + (size_t)e * 4);
            const int2 ij = *reinterpret_cast<const int2*>(edge_idx + (size_t)e * 2);
            sDst[tid] = ij.x;
            sSrc[tid] = ij.y;
        }
        __syncthreads();

        // phase B: w[col] = h @ Wfc2[:, col] for 4 edges
        float wv[4] = {0.f, 0.f, 0.f, 0.f};
#pragma unroll
        for (int k4 = 0; k4 < 16; ++k4) {
#pragma unroll
            for (int q = 0; q < 4; ++q) {
                const float4 h4 = *reinterpret_cast<const float4*>(&sH[q][k4 * 4]);
                wv[q] = fmaf(h4.x, wcol[4 * k4 + 0], wv[q]);
                wv[q] = fmaf(h4.y, wcol[4 * k4 + 1], wv[q]);
                wv[q] = fmaf(h4.z, wcol[4 * k4 + 2], wv[q]);
                wv[q] = fmaf(h4.w, wcol[4 * k4 + 3], wv[q]);
            }
        }

        // phase C: gather source node features, tensor product, stage to smem
#pragma unroll
        for (int q = 0; q < 4; ++q) {
            const float w = wv[q] * W_SCALE;
            const float* nrow = d_sv + (size_t)sSrc[q] * 256;
            const float4 sh = sSh[q];
            float* st = sOut[r][q];
            const int col = tid;
            if (col < 64) {                           // outA -> agg_s[0:64]
                st[col] = w * nrow[col] * sh.x;
            } else if (col < 128) {                   // outB -> agg_v m=u
                const int u = col - 64;
                const float b = w * nrow[u];
                st[128 + 3 * u + 0] = b * sh.y;
                st[128 + 3 * u + 1] = b * sh.z;
                st[128 + 3 * u + 2] = b * sh.w;
            } else if (col < 192) {                   // outC -> agg_v m=64+u
                const int u = col - 128;
                const float ws = w * sh.x;
                st[320 + 3 * u + 0] = ws * nrow[64 + 3 * u + 0];
                st[320 + 3 * u + 1] = ws * nrow[64 + 3 * u + 1];
                st[320 + 3 * u + 2] = ws * nrow[64 + 3 * u + 2];
            } else {                                  // outD -> agg_s[64:128]
                const int u = col - 192;
                const float x0 = nrow[64 + 3 * u + 0];
                const float x1 = nrow[64 + 3 * u + 1];
                const float x2 = nrow[64 + 3 * u + 2];
                st[64 + u] = w * INV_SQRT3_C * (x0 * sh.y + x1 * sh.z + x2 * sh.w);
            }
        }
        __syncthreads();

        // one 2KB bulk reduce-add per edge into agg[dst]
        if (tid < 4) {
            asm volatile("fence.proxy.async.shared::cta;" ::: "memory");
            float* gdst = d_agg + (size_t)sDst[tid] * 512;
            const unsigned saddr = smem_u32(&sOut[r][tid][0]);
            asm volatile(
                "cp.reduce.async.bulk.global.shared::cta.bulk_group.add.f32 [%0], [%1], %2;"
                :: "l"(gdst), "r"(saddr), "n"(2048) : "memory");
            asm volatile("cp.async.bulk.commit_group;" ::: "memory");
        }
    }
    if (tid < 4) asm volatile("cp.async.bulk.wait_group 0;" ::: "memory");
}

// ---------------------------------------------------------------------------
// out_s: out[n, w] = (agg_s @ W2s) * inv_mid * inv_nn + (t @ Wsc_s) * inv_uv
// 8 nodes / block-iter; thread = (w, group), each group handles 2 nodes.
// ---------------------------------------------------------------------------
__global__ void __launch_bounds__(256)
out_s_kernel(const float* __restrict__ node_feat,
             const float* __restrict__ node_attr,
             const float* __restrict__ W2s,
             const float* __restrict__ Wsc_s,
             float* __restrict__ out)
{
    extern __shared__ float sm[];
    float* sW2  = sm;             // 8192  (128x64)
    float* sWsc = sm + 8192;      // 32768 (512x64)
    float* sT   = sm + 40960;     // 8*512
    float* sAg  = sm + 45056;     // 8*128
    const int tid = threadIdx.x;
    for (int i = tid; i < 8192;  i += 256) sW2[i]  = W2s[i];
    for (int i = tid; i < 32768; i += 256) sWsc[i] = Wsc_s[i];
    __syncthreads();

    const int w = tid & 63, grp = tid >> 6;
    const int ngr = (N_NODES + 7) / 8;
    for (int g = blockIdx.x; g < ngr; g += gridDim.x) {
        const int n0 = g * 8;
        __syncthreads();
        for (int i = tid; i < 4096; i += 256) {
            const int nl = i >> 9, p = i & 511;
            const int n = n0 + nl;
            float v = 0.f;
            if (n < N_NODES)
                v = node_feat[(size_t)n * 256 + (p >> 3)] * node_attr[(size_t)n * 8 + (p & 7)];
            sT[i] = v;
        }
        for (int i = tid; i < 1024; i += 256) {
            const int nl = i >> 7;
            const int n = n0 + nl;
            sAg[i] = (n < N_NODES) ? d_agg[(size_t)n * 512 + (i & 127)] : 0.f;
        }
        __syncthreads();

        const float* t0  = sT  + (grp * 2) * 512;
        const float* t1  = t0 + 512;
        const float* a0p = sAg + (grp * 2) * 128;
        const float* a1p = a0p + 128;
        float a0 = 0.f, a1 = 0.f, b0 = 0.f, b1 = 0.f;
#pragma unroll 4
        for (int m4 = 0; m4 < 32; ++m4) {
            const float4 x0 = *reinterpret_cast<const float4*>(a0p + m4 * 4);
            const float4 x1 = *reinterpret_cast<const float4*>(a1p + m4 * 4);
            const float w0 = sW2[(4 * m4 + 0) * 64 + w];
            const float w1 = sW2[(4 * m4 + 1) * 64 + w];
            const float w2 = sW2[(4 * m4 + 2) * 64 + w];
            const float w3 = sW2[(4 * m4 + 3) * 64 + w];
            a0 = fmaf(x0.x, w0, a0); a1 = fmaf(x1.x, w0, a1);
            a0 = fmaf(x0.y, w1, a0); a1 = fmaf(x1.y, w1, a1);
            a0 = fmaf(x0.z, w2, a0); a1 = fmaf(x1.z, w2, a1);
            a0 = fmaf(x0.w, w3, a0); a1 = fmaf(x1.w, w3, a1);
        }
#pragma unroll 4
        for (int p4 = 0; p4 < 128; ++p4) {
            const float4 x0 = *reinterpret_cast<const float4*>(t0 + p4 * 4);
            const float4 x1 = *reinterpret_cast<const float4*>(t1 + p4 * 4);
            const float w0 = sWsc[(4 * p4 + 0) * 64 + w];
            const float w1 = sWsc[(4 * p4 + 1) * 64 + w];
            const float w2 = sWsc[(4 * p4 + 2) * 64 + w];
            const float w3 = sWsc[(4 * p4 + 3) * 64 + w];
            b0 = fmaf(x0.x, w0, b0); b1 = fmaf(x1.x, w0, b1);
            b0 = fmaf(x0.y, w1, b0); b1 = fmaf(x1.y, w1, b1);
            b0 = fmaf(x0.z, w2, b0); b1 = fmaf(x1.z, w2, b1);
            b0 = fmaf(x0.w, w3, b0); b1 = fmaf(x1.w, w3, b1);
        }
        const int na = n0 + grp * 2, nb = na + 1;
        if (na < N_NODES) out[(size_t)na * 256 + w] = a0 * SC_A_C + b0 * SC_B_C;
        if (nb < N_NODES) out[(size_t)nb * 256 + w] = a1 * SC_A_C + b1 * SC_B_C;
    }
}

// ---------------------------------------------------------------------------
// out_v: out[n, 64+3w+c] = (agg_v[:, :, c] @ W2v)*inv_mid*inv_nn + sc_v*inv_uv
// 4 nodes / block-iter; thread = (w, node-group), 3 components each.
// ---------------------------------------------------------------------------
__global__ void __launch_bounds__(256)
out_v_kernel(const float* __restrict__ node_feat,
             const float* __restrict__ node_attr,
             const float* __restrict__ W2v,
             const float* __restrict__ Wsc_v,
             float* __restrict__ out)
{
    extern __shared__ float sm[];
    float* sW2  = sm;            // 8192
    float* sWsc = sm + 8192;     // 32768
    float* sTv  = sm + 40960;    // 4*3*512 = 6144
    float* sAv  = sm + 47104;    // 4*3*128 = 1536
    const int tid = threadIdx.x;
    for (int i = tid; i < 8192;  i += 256) sW2[i]  = W2v[i];
    for (int i = tid; i < 32768; i += 256) sWsc[i] = Wsc_v[i];
    __syncthreads();

    const int w = tid & 63, grp = tid >> 6;
    const int ngr = (N_NODES + 3) / 4;
    for (int g = blockIdx.x; g < ngr; g += gridDim.x) {
        const int n0 = g * 4;
        __syncthreads();
        // tv planes: sTv[nl*1536 + c*512 + p] = v0[u][c] * attr[v]
        for (int i = tid; i < 6144; i += 256) {
            const int qq = i >> 9;          // 0..11
            const int nl = qq / 3, c = qq - nl * 3;
            const int p = i & 511;
            const int n = n0 + nl;
            float v = 0.f;
            if (n < N_NODES)
                v = node_feat[(size_t)n * 256 + 64 + 3 * (p >> 3) + c] *
                    node_attr[(size_t)n * 8 + (p & 7)];
            sTv[i] = v;
        }
        // agg_v planes: sAv[nl*384 + c*128 + m] = d_agg[n*512 + 128 + 3m + c]
        for (int nl = 0; nl < 4; ++nl) {
            const int n = n0 + nl;
            for (int j = tid; j < 384; j += 256) {
                const float v = (n < N_NODES) ? d_agg[(size_t)n * 512 + 128 + j] : 0.f;
                const int m = j / 3, c = j - m * 3;
                sAv[nl * 384 + c * 128 + m] = v;
            }
        }
        __syncthreads();

        const int n = n0 + grp;
        const float* tv = sTv + grp * 1536;
        const float* av = sAv + grp * 384;
        float aa0 = 0.f, aa1 = 0.f, aa2 = 0.f, bb0 = 0.f, bb1 = 0.f, bb2 = 0.f;
#pragma unroll 4
        for (int m4 = 0; m4 < 32; ++m4) {
            const float4 y0 = *reinterpret_cast<const float4*>(av + 0   + m4 * 4);
            const float4 y1 = *reinterpret_cast<const float4*>(av + 128 + m4 * 4);
            const float4 y2 = *reinterpret_cast<const float4*>(av + 256 + m4 * 4);
            const float w0 = sW2[(4 * m4 + 0) * 64 + w];
            const float w1 = sW2[(4 * m4 + 1) * 64 + w];
            const float w2 = sW2[(4 * m4 + 2) * 64 + w];
            const float w3 = sW2[(4 * m4 + 3) * 64 + w];
            aa0 = fmaf(y0.x, w0, aa0); aa1 = fmaf(y1.x, w0, aa1); aa2 = fmaf(y2.x, w0, aa2);
            aa0 = fmaf(y0.y, w1, aa0); aa1 = fmaf(y1.y, w1, aa1); aa2 = fmaf(y2.y, w1, aa2);
            aa0 = fmaf(y0.z, w2, aa0); aa1 = fmaf(y1.z, w2, aa1); aa2 = fmaf(y2.z, w2, aa2);
            aa0 = fmaf(y0.w, w3, aa0); aa1 = fmaf(y1.w, w3, aa1); aa2 = fmaf(y2.w, w3, aa2);
        }
#pragma unroll 2
        for (int p4 = 0; p4 < 128; ++p4) {
            const float4 y0 = *reinterpret_cast<const float4*>(tv + 0    + p4 * 4);
            const float4 y1 = *reinterpret_cast<const float4*>(tv + 512  + p4 * 4);
            const float4 y2 = *reinterpret_cast<const float4*>(tv + 1024 + p4 * 4);
            const float w0 = sWsc[(4 * p4 + 0) * 64 + w];
            const float w1 = sWsc[(4 * p4 + 1) * 64 + w];
            const float w2 = sWsc[(4 * p4 + 2) * 64 + w];
            const float w3 = sWsc[(4 * p4 + 3) * 64 + w];
            bb0 = fmaf(y0.x, w0, bb0); bb1 = fmaf(y1.x, w0, bb1); bb2 = fmaf(y2.x, w0, bb2);
            bb0 = fmaf(y0.y, w1, bb0); bb1 = fmaf(y1.y, w1, bb1); bb2 = fmaf(y2.y, w1, bb2);
            bb0 = fmaf(y0.z, w2, bb0); bb1 = fmaf(y1.z, w2, bb1); bb2 = fmaf(y2.z, w2, bb2);
            bb0 = fmaf(y0.w, w3, bb0); bb1 = fmaf(y1.w, w3, bb1); bb2 = fmaf(y2.w, w3, bb2);
        }
        if (n < N_NODES) {
            float* o = out + (size_t)n * 256 + 64 + 3 * w;
            o[0] = aa0 * SC_A_C + bb0 * SC_B_C;
            o[1] = aa1 * SC_A_C + bb1 * SC_B_C;
            o[2] = aa2 * SC_A_C + bb2 * SC_B_C;
        }
    }
}

// ---------------------------------------------------------------------------
extern "C" void kernel_launch(void* const* d_in, const int* /*in_sizes*/, int /*n_in*/,
                              void* d_out, int /*out_size*/)
{
    const float* node_feat  = (const float*)d_in[0];
    const float* node_attr  = (const float*)d_in[1];
    const float* edge_sh    = (const float*)d_in[2];
    const float* edge_basis = (const float*)d_in[3];
    const float* W1s        = (const float*)d_in[4];
    const float* W1v        = (const float*)d_in[5];
    const float* Wfc1       = (const float*)d_in[6];
    const float* Wfc2       = (const float*)d_in[7];
    const float* W2s        = (const float*)d_in[8];
    const float* W2v        = (const float*)d_in[9];
    const float* Wsc_s      = (const float*)d_in[10];
    const float* Wsc_v      = (const float*)d_in[11];
    const int*   edge_idx   = (const int*)d_in[12];
    float* out = (float*)d_out;

    cudaFuncSetAttribute(out_s_kernel, cudaFuncAttributeMaxDynamicSharedMemorySize, 46080 * 4);
    cudaFuncSetAttribute(out_v_kernel, cudaFuncAttributeMaxDynamicSharedMemorySize, 48640 * 4);

    zero_agg_kernel<<<(N_NODES * 128 + 255) / 256, 256>>>();
    nodeprep_kernel<<<304, 256>>>(node_feat, W1s, W1v);
    edge_kernel<<<304, 256>>>(edge_sh, edge_basis, Wfc1, Wfc2, edge_idx);
    out_s_kernel<<<152, 256, 46080 * 4>>>(node_feat, node_attr, W2s, Wsc_s, out);
    out_v_kernel<<<152, 256, 48640 * 4>>>(node_feat, node_attr, W2v, Wsc_v, out);
}

// round 4
// speedup vs baseline: 1.1096x; 1.1096x over previous
#include <cuda_runtime.h>
#include <cstdint>
#include <cstddef>

#define N_NODES 20000
#define N_EDGES 320000
#define EPB 8    // edges per block-iteration in edge kernel

#define LOG2_C       0.6931471805599453f
#define INV_SQRT3_C  0.5773502691896258f
#define INV_SQRT8_C  0.35355339059327373f
#define W_SCALE      0.125f
#define INV_MUL_C    0.125f
#define SC_A_C       0.02209708691207961f   // 1/sqrt(128) * 1/sqrt(16)
#define SC_B_C       0.04419417382415922f   // 1/sqrt(512)

__device__ __align__(1024) float d_sv[(size_t)N_NODES * 256];
__device__ __align__(1024) float d_agg[(size_t)N_NODES * 512];

__device__ __forceinline__ unsigned smem_u32(const void* p) {
    return (unsigned)__cvta_generic_to_shared(p);
}
__device__ __forceinline__ float4 ld4s(const float* p) {
    return *reinterpret_cast<const float4*>(p);
}

// ---------------------------------------------------------------------------
__global__ void zero_agg_kernel() {
    size_t i = (size_t)blockIdx.x * blockDim.x + threadIdx.x;
    float4* p = reinterpret_cast<float4*>(d_agg);
    if (i < (size_t)N_NODES * 128) p[i] = make_float4(0.f, 0.f, 0.f, 0.f);
}

// ---------------------------------------------------------------------------
// node prep: s = s0 @ W1s ; v = v0 @ W1v  (per component), scaled 1/8
// ---------------------------------------------------------------------------
__global__ void __launch_bounds__(256)
nodeprep_kernel(const float* __restrict__ node_feat,
                const float* __restrict__ W1s,
                const float* __restrict__ W1v)
{
    __shared__ float sW1s[4096];
    __shared__ float sW1v[4096];
    __shared__ float sNF[4][256];

    const int tid = threadIdx.x;
    for (int i = tid; i < 4096; i += 256) { sW1s[i] = W1s[i]; sW1v[i] = W1v[i]; }
    __syncthreads();

    const int ngroups = (N_NODES + 3) / 4;
    for (int g = blockIdx.x; g < ngroups; g += gridDim.x) {
        const int n0 = g * 4;
        __syncthreads();
        for (int i = tid; i < 1024; i += 256) {
            const int nl = i >> 8, j = i & 255;
            const int n = n0 + nl;
            sNF[nl][j] = (n < N_NODES) ? node_feat[(size_t)n * 256 + j] : 0.f;
        }
        __syncthreads();
        const int nl = tid >> 6, w = tid & 63;
        const int n = n0 + nl;
        if (n < N_NODES) {
            float sacc = 0.f, v0a = 0.f, v1a = 0.f, v2a = 0.f;
#pragma unroll
            for (int u = 0; u < 64; ++u) {
                const float ws = sW1s[u * 64 + w];
                const float wv = sW1v[u * 64 + w];
                sacc = fmaf(sNF[nl][u], ws, sacc);
                v0a  = fmaf(sNF[nl][64 + 3 * u + 0], wv, v0a);
                v1a  = fmaf(sNF[nl][64 + 3 * u + 1], wv, v1a);
                v2a  = fmaf(sNF[nl][64 + 3 * u + 2], wv, v2a);
            }
            float* o = d_sv + (size_t)n * 256;
            o[w] = sacc * INV_MUL_C;
            o[64 + 3 * w + 0] = v0a * INV_MUL_C;
            o[64 + 3 * w + 1] = v1a * INV_MUL_C;
            o[64 + 3 * w + 2] = v2a * INV_MUL_C;
        }
    }
}

// ---------------------------------------------------------------------------
// edge kernel: fused FC1 -> softplus -> FC2 -> gather -> tensor product ->
// bulk-reduce scatter. EPB=8 edges per block iteration.
// ---------------------------------------------------------------------------
__global__ void __launch_bounds__(256, 2)
edge_kernel(const float* __restrict__ edge_sh,
            const float* __restrict__ edge_basis,
            const float* __restrict__ Wfc1,
            const float* __restrict__ Wfc2,
            const int*   __restrict__ edge_idx)
{
    __shared__ float sWfc1[512];
    __shared__ __align__(16) float sH[EPB][64];
    __shared__ __align__(16) float sOut[2][EPB][512];
    __shared__ int    sSrc[EPB];
    __shared__ int    sDst[EPB];
    __shared__ float4 sSh[EPB];

    const int tid = threadIdx.x;

    float wcol[64];
#pragma unroll
    for (int k = 0; k < 64; ++k) wcol[k] = Wfc2[k * 256 + tid];
    for (int i = tid; i < 512; i += 256) sWfc1[i] = Wfc1[i];
    __syncthreads();

    const int niter = N_EDGES / EPB;
    int li = 0;
    for (int it = blockIdx.x; it < niter; it += gridDim.x, ++li) {
        const int e0 = it * EPB;
        const int r = li & 1;

        if (tid < EPB) asm volatile("cp.async.bulk.wait_group 1;" ::: "memory");

        // phase A: h for EPB edges (EPB*64 = 512 values, 2 per thread)
#pragma unroll
        for (int i = tid; i < EPB * 64; i += 256) {
            const int el = i >> 6, k = i & 63;
            const int e = e0 + el;
            const float4 b0 = __ldg(reinterpret_cast<const float4*>(edge_basis + (size_t)e * 8));
            const float4 b1 = __ldg(reinterpret_cast<const float4*>(edge_basis + (size_t)e * 8) + 1);
            float acc;
            acc = b0.x * sWfc1[0 * 64 + k];
            acc = fmaf(b0.y, sWfc1[1 * 64 + k], acc);
            acc = fmaf(b0.z, sWfc1[2 * 64 + k], acc);
            acc = fmaf(b0.w, sWfc1[3 * 64 + k], acc);
            acc = fmaf(b1.x, sWfc1[4 * 64 + k], acc);
            acc = fmaf(b1.y, sWfc1[5 * 64 + k], acc);
            acc = fmaf(b1.z, sWfc1[6 * 64 + k], acc);
            acc = fmaf(b1.w, sWfc1[7 * 64 + k], acc);
            acc *= INV_SQRT8_C;
            const float sp = fmaxf(acc, 0.f) + log1pf(__expf(-fabsf(acc)));
            sH[el][k] = sp - LOG2_C;
        }
        if (tid < EPB) {
            const int e = e0 + tid;
            sSh[tid] = *reinterpret_cast<const float4*>(edge_sh + (size_t)e * 4);
            const int2 ij = *reinterpret_cast<const int2*>(edge_idx + (size_t)e * 2);
            sDst[tid] = ij.x;
            sSrc[tid] = ij.y;
        }
        __syncthreads();

        // phase B: w[col] for EPB edges (col = tid, weights in registers)
        float wv[EPB];
#pragma unroll
        for (int q = 0; q < EPB; ++q) wv[q] = 0.f;
#pragma unroll
        for (int k4 = 0; k4 < 16; ++k4) {
#pragma unroll
            for (int q = 0; q < EPB; ++q) {
                const float4 h4 = ld4s(&sH[q][k4 * 4]);
                wv[q] = fmaf(h4.x, wcol[4 * k4 + 0], wv[q]);
                wv[q] = fmaf(h4.y, wcol[4 * k4 + 1], wv[q]);
                wv[q] = fmaf(h4.z, wcol[4 * k4 + 2], wv[q]);
                wv[q] = fmaf(h4.w, wcol[4 * k4 + 3], wv[q]);
            }
        }

        // phase C: gather + tensor product -> staging smem
#pragma unroll
        for (int q = 0; q < EPB; ++q) {
            const float w = wv[q] * W_SCALE;
            const float* nrow = d_sv + (size_t)sSrc[q] * 256;
            const float4 sh = sSh[q];
            float* st = sOut[r][q];
            const int col = tid;
            if (col < 64) {
                st[col] = w * nrow[col] * sh.x;
            } else if (col < 128) {
                const int u = col - 64;
                const float b = w * nrow[u];
                st[128 + 3 * u + 0] = b * sh.y;
                st[128 + 3 * u + 1] = b * sh.z;
                st[128 + 3 * u + 2] = b * sh.w;
            } else if (col < 192) {
                const int u = col - 128;
                const float ws = w * sh.x;
                st[320 + 3 * u + 0] = ws * nrow[64 + 3 * u + 0];
                st[320 + 3 * u + 1] = ws * nrow[64 + 3 * u + 1];
                st[320 + 3 * u + 2] = ws * nrow[64 + 3 * u + 2];
            } else {
                const int u = col - 192;
                const float x0 = nrow[64 + 3 * u + 0];
                const float x1 = nrow[64 + 3 * u + 1];
                const float x2 = nrow[64 + 3 * u + 2];
                st[64 + u] = w * INV_SQRT3_C * (x0 * sh.y + x1 * sh.z + x2 * sh.w);
            }
        }
        __syncthreads();

        if (tid < EPB) {
            asm volatile("fence.proxy.async.shared::cta;" ::: "memory");
            float* gdst = d_agg + (size_t)sDst[tid] * 512;
            const unsigned saddr = smem_u32(&sOut[r][tid][0]);
            asm volatile(
                "cp.reduce.async.bulk.global.shared::cta.bulk_group.add.f32 [%0], [%1], %2;"
                :: "l"(gdst), "r"(saddr), "n"(2048) : "memory");
            asm volatile("cp.async.bulk.commit_group;" ::: "memory");
        }
    }
    if (tid < EPB) asm volatile("cp.async.bulk.wait_group 0;" ::: "memory");
}

// ---------------------------------------------------------------------------
// out_s: transposed padded weights in smem, 16 nodes/iter, 4 nodes/thread.
// smem floats: W2t 64*132=8448 | Wsct 64*516=33024 | sT 16*512 | sAg 16*128
// ---------------------------------------------------------------------------
__global__ void __launch_bounds__(256)
out_s_kernel(const float* __restrict__ node_feat,
             const float* __restrict__ node_attr,
             const float* __restrict__ W2s,
             const float* __restrict__ Wsc_s,
             float* __restrict__ out)
{
    extern __shared__ float sm[];
    float* sW2t  = sm;                 // 8448
    float* sWsct = sm + 8448;          // 33024
    float* sT    = sm + 41472;         // 8192
    float* sAg   = sm + 49664;         // 2048  (total 51712 floats)
    const int tid = threadIdx.x;

    for (int i = tid; i < 8192;  i += 256) { const int k = i >> 6, w = i & 63; sW2t[w * 132 + k]  = W2s[i]; }
    for (int i = tid; i < 32768; i += 256) { const int p = i >> 6, w = i & 63; sWsct[w * 516 + p] = Wsc_s[i]; }
    __syncthreads();

    const int w = tid & 63, grp = tid >> 6;
    const float* w2row  = sW2t  + w * 132;
    const float* wscrow = sWsct + w * 516;
    const int ngr = N_NODES / 16;   // 1250
    for (int g = blockIdx.x; g < ngr; g += gridDim.x) {
        const int n0 = g * 16;
        __syncthreads();
        for (int i = tid; i < 8192; i += 256) {
            const int nl = i >> 9, p = i & 511;
            const int n = n0 + nl;
            sT[i] = node_feat[(size_t)n * 256 + (p >> 3)] * node_attr[(size_t)n * 8 + (p & 7)];
        }
        for (int i = tid; i < 2048; i += 256) {
            const int nl = i >> 7;
            sAg[i] = d_agg[(size_t)(n0 + nl) * 512 + (i & 127)];
        }
        __syncthreads();

        float a[4] = {0.f, 0.f, 0.f, 0.f};
        float b[4] = {0.f, 0.f, 0.f, 0.f};
#pragma unroll 4
        for (int k4 = 0; k4 < 32; ++k4) {
            const float4 wv = ld4s(w2row + 4 * k4);
#pragma unroll
            for (int j = 0; j < 4; ++j) {
                const float4 x = ld4s(sAg + (grp * 4 + j) * 128 + 4 * k4);
                a[j] = fmaf(x.x, wv.x, a[j]);
                a[j] = fmaf(x.y, wv.y, a[j]);
                a[j] = fmaf(x.z, wv.z, a[j]);
                a[j] = fmaf(x.w, wv.w, a[j]);
            }
        }
#pragma unroll 4
        for (int p4 = 0; p4 < 128; ++p4) {
            const float4 wv = ld4s(wscrow + 4 * p4);
#pragma unroll
            for (int j = 0; j < 4; ++j) {
                const float4 x = ld4s(sT + (grp * 4 + j) * 512 + 4 * p4);
                b[j] = fmaf(x.x, wv.x, b[j]);
                b[j] = fmaf(x.y, wv.y, b[j]);
                b[j] = fmaf(x.z, wv.z, b[j]);
                b[j] = fmaf(x.w, wv.w, b[j]);
            }
        }
#pragma unroll
        for (int j = 0; j < 4; ++j) {
            const int n = n0 + grp * 4 + j;
            out[(size_t)n * 256 + w] = a[j] * SC_A_C + b[j] * SC_B_C;
        }
    }
}

// ---------------------------------------------------------------------------
// out_v: transposed padded weights, 4 nodes/iter, 1 node/thread-group,
// 3 vector components per thread (6 FMA chains).
// smem floats: W2t 8448 | Wsct 33024 | sTv 4*1536=6144 | sAv 4*384=1536
// ---------------------------------------------------------------------------
__global__ void __launch_bounds__(256)
out_v_kernel(const float* __restrict__ node_feat,
             const float* __restrict__ node_attr,
             const float* __restrict__ W2v,
             const float* __restrict__ Wsc_v,
             float* __restrict__ out)
{
    extern __shared__ float sm[];
    float* sW2t  = sm;                 // 8448
    float* sWsct = sm + 8448;          // 33024
    float* sTv   = sm + 41472;         // 6144
    float* sAv   = sm + 47616;         // 1536  (total 49152 floats)
    const int tid = threadIdx.x;

    for (int i = tid; i < 8192;  i += 256) { const int k = i >> 6, w = i & 63; sW2t[w * 132 + k]  = W2v[i]; }
    for (int i = tid; i < 32768; i += 256) { const int p = i >> 6, w = i & 63; sWsct[w * 516 + p] = Wsc_v[i]; }
    __syncthreads();

    const int w = tid & 63, grp = tid >> 6;
    const float* w2row  = sW2t  + w * 132;
    const float* wscrow = sWsct + w * 516;
    const int ngr = N_NODES / 4;   // 5000
    for (int g = blockIdx.x; g < ngr; g += gridDim.x) {
        const int n0 = g * 4;
        __syncthreads();
        // sTv[nl*1536 + c*512 + p] = v0[n][p>>3][c] * attr[n][p&7]
        for (int i = tid; i < 6144; i += 256) {
            const int qq = i >> 9;
            const int nl = qq / 3, c = qq - nl * 3;
            const int p = i & 511;
            const int n = n0 + nl;
            sTv[i] = node_feat[(size_t)n * 256 + 64 + 3 * (p >> 3) + c] *
                     node_attr[(size_t)n * 8 + (p & 7)];
        }
        // sAv[nl*384 + c*128 + m] = d_agg[n*512 + 128 + 3m + c]
        // NOTE: slab size 384 is NOT a power of two — must use true div/mod.
        for (int i = tid; i < 1536; i += 256) {
            const int nl = i / 384;
            const int j  = i - nl * 384;
            const float v = d_agg[(size_t)(n0 + nl) * 512 + 128 + j];
            const int m = j / 3, c = j - m * 3;
            sAv[nl * 384 + c * 128 + m] = v;
        }
        __syncthreads();

        const float* tv = sTv + grp * 1536;
        const float* av = sAv + grp * 384;
        float aa0 = 0.f, aa1 = 0.f, aa2 = 0.f, bb0 = 0.f, bb1 = 0.f, bb2 = 0.f;
#pragma unroll 4
        for (int k4 = 0; k4 < 32; ++k4) {
            const float4 wv = ld4s(w2row + 4 * k4);
            const float4 y0 = ld4s(av + 0   + 4 * k4);
            const float4 y1 = ld4s(av + 128 + 4 * k4);
            const float4 y2 = ld4s(av + 256 + 4 * k4);
            aa0 = fmaf(y0.x, wv.x, aa0); aa1 = fmaf(y1.x, wv.x, aa1); aa2 = fmaf(y2.x, wv.x, aa2);
            aa0 = fmaf(y0.y, wv.y, aa0); aa1 = fmaf(y1.y, wv.y, aa1); aa2 = fmaf(y2.y, wv.y, aa2);
            aa0 = fmaf(y0.z, wv.z, aa0); aa1 = fmaf(y1.z, wv.z, aa1); aa2 = fmaf(y2.z, wv.z, aa2);
            aa0 = fmaf(y0.w, wv.w, aa0); aa1 = fmaf(y1.w, wv.w, aa1); aa2 = fmaf(y2.w, wv.w, aa2);
        }
#pragma unroll 4
        for (int p4 = 0; p4 < 128; ++p4) {
            const float4 wv = ld4s(wscrow + 4 * p4);
            const float4 y0 = ld4s(tv + 0    + 4 * p4);
            const float4 y1 = ld4s(tv + 512  + 4 * p4);
            const float4 y2 = ld4s(tv + 1024 + 4 * p4);
            bb0 = fmaf(y0.x, wv.x, bb0); bb1 = fmaf(y1.x, wv.x, bb1); bb2 = fmaf(y2.x, wv.x, bb2);
            bb0 = fmaf(y0.y, wv.y, bb0); bb1 = fmaf(y1.y, wv.y, bb1); bb2 = fmaf(y2.y, wv.y, bb2);
            bb0 = fmaf(y0.z, wv.z, bb0); bb1 = fmaf(y1.z, wv.z, bb1); bb2 = fmaf(y2.z, wv.z, bb2);
            bb0 = fmaf(y0.w, wv.w, bb0); bb1 = fmaf(y1.w, wv.w, bb1); bb2 = fmaf(y2.w, wv.w, bb2);
        }
        const int n = n0 + grp;
        float* o = out + (size_t)n * 256 + 64 + 3 * w;
        o[0] = aa0 * SC_A_C + bb0 * SC_B_C;
        o[1] = aa1 * SC_A_C + bb1 * SC_B_C;
        o[2] = aa2 * SC_A_C + bb2 * SC_B_C;
    }
}

// ---------------------------------------------------------------------------
extern "C" void kernel_launch(void* const* d_in, const int* /*in_sizes*/, int /*n_in*/,
                              void* d_out, int /*out_size*/)
{
    const float* node_feat  = (const float*)d_in[0];
    const float* node_attr  = (const float*)d_in[1];
    const float* edge_sh    = (const float*)d_in[2];
    const float* edge_basis = (const float*)d_in[3];
    const float* W1s        = (const float*)d_in[4];
    const float* W1v        = (const float*)d_in[5];
    const float* Wfc1       = (const float*)d_in[6];
    const float* Wfc2       = (const float*)d_in[7];
    const float* W2s        = (const float*)d_in[8];
    const float* W2v        = (const float*)d_in[9];
    const float* Wsc_s      = (const float*)d_in[10];
    const float* Wsc_v      = (const float*)d_in[11];
    const int*   edge_idx   = (const int*)d_in[12];
    float* out = (float*)d_out;

    cudaFuncSetAttribute(out_s_kernel, cudaFuncAttributeMaxDynamicSharedMemorySize, 51712 * 4);
    cudaFuncSetAttribute(out_v_kernel, cudaFuncAttributeMaxDynamicSharedMemorySize, 49152 * 4);

    zero_agg_kernel<<<(N_NODES * 128 + 255) / 256, 256>>>();
    nodeprep_kernel<<<296, 256>>>(node_feat, W1s, W1v);
    edge_kernel<<<296, 256>>>(edge_sh, edge_basis, Wfc1, Wfc2, edge_idx);
    out_s_kernel<<<148, 256, 51712 * 4>>>(node_feat, node_attr, W2s, Wsc_s, out);
    out_v_kernel<<<148, 256, 49152 * 4>>>(node_feat, node_attr, W2v, Wsc_v, out);
}